// round 3
// baseline (speedup 1.0000x reference)
#include <cuda_runtime.h>
#include <cuda_bf16.h>
#include <cstdint>

// out = P5(x) / Q4(x) elementwise over x[4, 4096, 2048], 8 groups of 256 along D.
// Packed f32x2 math (Blackwell), ulonglong2 streaming (pairs pre-packed),
// segment-split items so all 4 items/thread share one group.

#define THREADS 256
#define ITEMS   4

typedef unsigned long long u64;

__device__ __forceinline__ u64 pack2(float x, float y) {
    u64 r; asm("mov.b64 %0, {%1, %2};" : "=l"(r) : "f"(x), "f"(y)); return r;
}
__device__ __forceinline__ void unpack2(u64 v, float& x, float& y) {
    asm("mov.b64 {%0, %1}, %2;" : "=f"(x), "=f"(y) : "l"(v));
}
__device__ __forceinline__ u64 fma2(u64 a, u64 b, u64 c) {
    u64 d; asm("fma.rn.f32x2 %0, %1, %2, %3;" : "=l"(d) : "l"(a), "l"(b), "l"(c)); return d;
}
__device__ __forceinline__ u64 mul2(u64 a, u64 b) {
    u64 d; asm("mul.rn.f32x2 %0, %1, %2;" : "=l"(d) : "l"(a), "l"(b)); return d;
}
__device__ __forceinline__ float rcpf(float x) {
    float r; asm("rcp.approx.f32 %0, %1;" : "=f"(r) : "f"(x)); return r;
}

// One float-pair: rational(z) for both lanes of the packed register.
__device__ __forceinline__ u64 rational2(u64 z,
    u64 aa0, u64 aa1, u64 aa2, u64 aa3, u64 aa4, u64 aa5,
    u64 cc1, u64 cc2, u64 cc3, u64 cc4, u64 one2)
{
    u64 num = fma2(aa5, z, aa4);
    num = fma2(num, z, aa3);
    num = fma2(num, z, aa2);
    num = fma2(num, z, aa1);
    num = fma2(num, z, aa0);

    u64 den = fma2(cc4, z, cc3);
    den = fma2(den, z, cc2);
    den = fma2(den, z, cc1);
    den = fma2(den, z, one2);

    float d0, d1;
    unpack2(den, d0, d1);
    u64 r = pack2(rcpf(d0), rcpf(d1));
    return mul2(num, r);
}

// Fast path: requires n4 % (ITEMS*THREADS) == 0 and (n4/ITEMS) % 512 == 0,
// so each thread's ITEMS elements (strided by seg) share one group.
__global__ __launch_bounds__(THREADS, 5)
void kat_rational_seg(const ulonglong2* __restrict__ x4,
                      const float*  __restrict__ wnum,
                      const float*  __restrict__ wden,
                      ulonglong2* __restrict__ out4,
                      int seg)                 // float4s per segment
{
    int t = blockIdx.x * THREADS + threadIdx.x;

    // Batch all stream loads up front (MLP = ITEMS).
    ulonglong2 v[ITEMS];
    #pragma unroll
    for (int j = 0; j < ITEMS; ++j)
        v[j] = __ldcs(&x4[t + j * seg]);

    // Coefficients: 3 vector loads, all warp-uniform.
    float4 a03 = __ldg((const float4*)wnum);
    float  a4f = __ldg(wnum + 4), a5f = __ldg(wnum + 5);
    int g = (t >> 6) & 7;                       // 64 float4 per group chunk
    float4 bb = __ldg((const float4*)(wden + g * 4));

    u64 aa0 = pack2(a03.x, a03.x), aa1 = pack2(a03.y, a03.y);
    u64 aa2 = pack2(a03.z, a03.z), aa3 = pack2(a03.w, a03.w);
    u64 aa4 = pack2(a4f, a4f),     aa5 = pack2(a5f, a5f);
    u64 cc1 = pack2(fabsf(bb.x), fabsf(bb.x));
    u64 cc2 = pack2(fabsf(bb.y), fabsf(bb.y));
    u64 cc3 = pack2(fabsf(bb.z), fabsf(bb.z));
    u64 cc4 = pack2(fabsf(bb.w), fabsf(bb.w));
    u64 one2 = pack2(1.0f, 1.0f);

    #pragma unroll
    for (int j = 0; j < ITEMS; ++j) {
        ulonglong2 o;
        o.x = rational2(v[j].x, aa0,aa1,aa2,aa3,aa4,aa5, cc1,cc2,cc3,cc4, one2);
        o.y = rational2(v[j].y, aa0,aa1,aa2,aa3,aa4,aa5, cc1,cc2,cc3,cc4, one2);
        __stcs(&out4[t + j * seg], o);
    }
}

// Generic fallback (any size), scalar path.
__global__ __launch_bounds__(THREADS)
void kat_rational_generic(const float* __restrict__ x,
                          const float* __restrict__ wnum,
                          const float* __restrict__ wden,
                          float* __restrict__ out,
                          int n)
{
    int i = blockIdx.x * THREADS + threadIdx.x;
    if (i >= n) return;
    int g = (i % 2048) / 256;
    float a0 = wnum[0], a1 = wnum[1], a2 = wnum[2], a3 = wnum[3], a4 = wnum[4], a5 = wnum[5];
    float c1 = fabsf(wden[g*4+0]), c2 = fabsf(wden[g*4+1]);
    float c3 = fabsf(wden[g*4+2]), c4 = fabsf(wden[g*4+3]);
    float z = x[i];
    float num = fmaf(fmaf(fmaf(fmaf(fmaf(a5, z, a4), z, a3), z, a2), z, a1), z, a0);
    float den = fmaf(fmaf(fmaf(fmaf(c4, z, c3), z, c2), z, c1), z, 1.0f);
    out[i] = __fdividef(num, den);
}

extern "C" void kernel_launch(void* const* d_in, const int* in_sizes, int n_in,
                              void* d_out, int out_size)
{
    const float* x    = (const float*)d_in[0];
    const float* wnum = (const float*)d_in[1];
    const float* wden = (const float*)d_in[2];
    float* out        = (float*)d_out;

    int n  = in_sizes[0];     // 33,554,432
    int n4 = n >> 2;          // 8,388,608 float4s
    int seg = n4 / ITEMS;     // 2,097,152 float4s per segment

    bool fast = (n4 % (ITEMS * THREADS) == 0) && (seg % 512 == 0);
    if (fast) {
        int blocks = seg / THREADS;   // 8192
        kat_rational_seg<<<blocks, THREADS>>>((const ulonglong2*)x, wnum, wden,
                                              (ulonglong2*)out, seg);
    } else {
        int blocks = (n + THREADS - 1) / THREADS;
        kat_rational_generic<<<blocks, THREADS>>>(x, wnum, wden, out, n);
    }
}